// round 2
// baseline (speedup 1.0000x reference)
#include <cuda_runtime.h>
#include <cstddef>

// Problem constants
#define CDIM   1024
#define NTOK   2112          // n + nl
#define NX     2048          // n
#define NL     64            // nl
#define NBT    32            // b*t
#define INNER  512           // heads*dim_head
#define HEADS  8
#define DH     64
#define MROWS  67584         // NBT * NTOK
#define QROWS  2048          // NBT * NL
#define SCALE  0.125f        // dh^-0.5

// Scratch (allocation-free rule: __device__ globals)
__device__ float g_kvin[(size_t)MROWS * CDIM];     // normalized concat(x, latents)
__device__ float g_kv  [(size_t)MROWS * CDIM];     // kvin @ Wkv
__device__ float g_lat [(size_t)QROWS * CDIM];     // normalized latents (contiguous)
__device__ float g_q   [(size_t)QROWS * INNER];    // lat @ Wq
__device__ float g_sim [(size_t)NBT * HEADS * NL * NTOK]; // scores -> probs (in place)
__device__ float g_ao  [(size_t)QROWS * INNER];    // attn @ v

// ---------------------------------------------------------------------------
// LayerNorm: one block per row (1024 elems, 256 threads, float4)
// Writes into g_kvin at concat layout; latent rows also into g_lat.
// ---------------------------------------------------------------------------
__global__ void __launch_bounds__(256) ln_kernel(
    const float* __restrict__ x, const float* __restrict__ lat,
    const float* __restrict__ mw, const float* __restrict__ mb,
    const float* __restrict__ lw, const float* __restrict__ lb)
{
    int r   = blockIdx.x;
    int bt  = r / NTOK;
    int tok = r - bt * NTOK;

    const float *src, *w, *bias;
    float* dst2 = nullptr;
    if (tok < NX) {
        src = x + (size_t)(bt * NX + tok) * CDIM;
        w = mw; bias = mb;
    } else {
        int lr = bt * NL + (tok - NX);
        src = lat + (size_t)lr * CDIM;
        w = lw; bias = lb;
        dst2 = g_lat + (size_t)lr * CDIM;
    }
    float* dst = g_kvin + (size_t)r * CDIM;

    int tid = threadIdx.x;
    float4 v = ((const float4*)src)[tid];
    float s  = v.x + v.y + v.z + v.w;
    float ss = v.x*v.x + v.y*v.y + v.z*v.z + v.w*v.w;

    __shared__ float sh_s[8], sh_ss[8];
    #pragma unroll
    for (int o = 16; o; o >>= 1) {
        s  += __shfl_xor_sync(0xffffffffu, s,  o);
        ss += __shfl_xor_sync(0xffffffffu, ss, o);
    }
    if ((tid & 31) == 0) { sh_s[tid >> 5] = s; sh_ss[tid >> 5] = ss; }
    __syncthreads();
    float ts = 0.f, tss = 0.f;
    #pragma unroll
    for (int i = 0; i < 8; ++i) { ts += sh_s[i]; tss += sh_ss[i]; }

    float mean = ts * (1.0f / CDIM);
    float var  = tss * (1.0f / CDIM) - mean * mean;
    float inv  = rsqrtf(var + 1e-5f);

    float4 wv = ((const float4*)w)[tid];
    float4 bv = ((const float4*)bias)[tid];
    float4 o;
    o.x = (v.x - mean) * inv * wv.x + bv.x;
    o.y = (v.y - mean) * inv * wv.y + bv.y;
    o.z = (v.z - mean) * inv * wv.z + bv.z;
    o.w = (v.w - mean) * inv * wv.w + bv.w;
    ((float4*)dst)[tid] = o;
    if (dst2) ((float4*)dst2)[tid] = o;
}

// ---------------------------------------------------------------------------
// fp32 SGEMM, software-pipelined: C(M,N) = A(M,K) @ B(K,N), row-major.
// 128x128 block tile, BK=8, 256 threads, 8x8 micro-tile, double-buffered
// smem with global->register prefetch (one __syncthreads per K-slice).
// MODE selects operands from __device__ globals (no cudaGetSymbolAddress):
//   MODE 0: g_kvin @ Bw -> g_kv
//   MODE 1: g_lat  @ Bw -> g_q
//   MODE 2: g_ao   @ Bw -> Cext
// Requires M%128==0, N%128==0, K%8==0 (true for all three calls).
// ---------------------------------------------------------------------------
template<int MODE>
__global__ void __launch_bounds__(256) sgemm_kernel(
    const float* __restrict__ Bw, float* __restrict__ Cext,
    int M, int N, int K)
{
    const float* A;
    float* C;
    if (MODE == 0)      { A = g_kvin; C = g_kv; }
    else if (MODE == 1) { A = g_lat;  C = g_q; }
    else                { A = g_ao;   C = Cext; }

    __shared__ float As[2][8][128];
    __shared__ float Bs[2][8][128];

    int tid = threadIdx.x;
    int bx = blockIdx.x, by = blockIdx.y;
    int tr = tid >> 4, tc = tid & 15;

    const float* Ab = A  + (size_t)by * 128 * K;
    const float* Bb = Bw + bx * 128;

    int a_row = tid >> 1;            // 0..127
    int a_col = (tid & 1) << 2;      // 0 or 4
    int b_row = tid >> 5;            // 0..7
    int b_col = (tid & 31) << 2;     // 0..124

    // Preload first K-slice into buffer 0
    {
        float4 av = *(const float4*)(Ab + (size_t)a_row * K + a_col);
        As[0][a_col + 0][a_row] = av.x;
        As[0][a_col + 1][a_row] = av.y;
        As[0][a_col + 2][a_row] = av.z;
        As[0][a_col + 3][a_row] = av.w;
        *(float4*)&Bs[0][b_row][b_col] =
            *(const float4*)(Bb + (size_t)b_row * N + b_col);
    }
    __syncthreads();

    float acc[8][8] = {};
    int buf = 0;

    for (int k0 = 0; k0 < K; k0 += 8) {
        // Prefetch next K-slice into registers (overlaps with compute below)
        float4 an, bn;
        bool has_next = (k0 + 8) < K;
        if (has_next) {
            an = *(const float4*)(Ab + (size_t)a_row * K + (k0 + 8) + a_col);
            bn = *(const float4*)(Bb + (size_t)(k0 + 8 + b_row) * N + b_col);
        }

        #pragma unroll
        for (int k = 0; k < 8; ++k) {
            float ra[8], rb[8];
            *(float4*)(ra)     = *(const float4*)&As[buf][k][tr * 4];
            *(float4*)(ra + 4) = *(const float4*)&As[buf][k][64 + tr * 4];
            *(float4*)(rb)     = *(const float4*)&Bs[buf][k][tc * 4];
            *(float4*)(rb + 4) = *(const float4*)&Bs[buf][k][64 + tc * 4];
            #pragma unroll
            for (int i = 0; i < 8; ++i)
                #pragma unroll
                for (int j = 0; j < 8; ++j)
                    acc[i][j] += ra[i] * rb[j];
        }

        if (has_next) {
            As[buf ^ 1][a_col + 0][a_row] = an.x;
            As[buf ^ 1][a_col + 1][a_row] = an.y;
            As[buf ^ 1][a_col + 2][a_row] = an.z;
            As[buf ^ 1][a_col + 3][a_row] = an.w;
            *(float4*)&Bs[buf ^ 1][b_row][b_col] = bn;
        }
        __syncthreads();
        buf ^= 1;
    }

    #pragma unroll
    for (int i = 0; i < 8; ++i) {
        int r = (i < 4) ? (tr * 4 + i) : (64 + tr * 4 + (i - 4));
        float* Crow = C + (size_t)(by * 128 + r) * N + bx * 128;
        *(float4*)(Crow + tc * 4)      = make_float4(acc[i][0], acc[i][1], acc[i][2], acc[i][3]);
        *(float4*)(Crow + 64 + tc * 4) = make_float4(acc[i][4], acc[i][5], acc[i][6], acc[i][7]);
    }
}

// ---------------------------------------------------------------------------
// sim = scale * q @ k^T + mask  per (bt, h); tiles of 64 keys.
// grid (256, 33), block 256. Output g_sim[(bth, i, j)].
// ---------------------------------------------------------------------------
__global__ void __launch_bounds__(256) sim_kernel(const int* __restrict__ mask)
{
    int bth = blockIdx.x, jc = blockIdx.y;
    int bt = bth >> 3, h = bth & 7;
    int b  = bt >> 2;                // bt = b*4 + t
    int j0 = jc * 64;

    __shared__ float qs[64][65];
    __shared__ float ks[64][65];
    __shared__ float msk[64];

    int tid = threadIdx.x;
    #pragma unroll
    for (int it = 0; it < 4; ++it) {
        int idx = tid + it * 256;            // 0..1023 float4 slots of a 64x64 tile
        int i = idx >> 4, d4 = (idx & 15) << 2;
        float4 v = *(const float4*)(g_q + (size_t)(bt * NL + i) * INNER + h * DH + d4);
        qs[i][d4] = v.x; qs[i][d4 + 1] = v.y; qs[i][d4 + 2] = v.z; qs[i][d4 + 3] = v.w;
        float4 u = *(const float4*)(g_kv + (size_t)(bt * NTOK + j0 + i) * CDIM + h * DH + d4);
        ks[i][d4] = u.x; ks[i][d4 + 1] = u.y; ks[i][d4 + 2] = u.z; ks[i][d4 + 3] = u.w;
    }
    if (tid < 64) {
        int jg = j0 + tid;
        float m = 0.f;
        if (jg < NX && mask[b * NX + jg] == 1) m = -1e30f;
        msk[tid] = m;
    }
    __syncthreads();

    int ii = tid >> 4, jj = tid & 15;
    float acc[4][4] = {};
    #pragma unroll 16
    for (int d = 0; d < 64; ++d) {
        float ra[4], rb[4];
        #pragma unroll
        for (int a = 0; a < 4; ++a) ra[a] = qs[a * 16 + ii][d];
        #pragma unroll
        for (int c = 0; c < 4; ++c) rb[c] = ks[c * 16 + jj][d];
        #pragma unroll
        for (int a = 0; a < 4; ++a)
            #pragma unroll
            for (int c = 0; c < 4; ++c)
                acc[a][c] += ra[a] * rb[c];
    }

    #pragma unroll
    for (int a = 0; a < 4; ++a)
        #pragma unroll
        for (int c = 0; c < 4; ++c) {
            int i = a * 16 + ii, j = c * 16 + jj;
            g_sim[((size_t)bth * NL + i) * NTOK + j0 + j] = acc[a][c] * SCALE + msk[j];
        }
}

// ---------------------------------------------------------------------------
// Row softmax over NTOK=2112, in place in g_sim. One block per row.
// ---------------------------------------------------------------------------
__global__ void __launch_bounds__(256) softmax_kernel()
{
    int row = blockIdx.x;
    float* p = g_sim + (size_t)row * NTOK;
    int tid = threadIdx.x;

    float vals[9];
    int cnt = 0;
    float mx = -3.0e38f;
    for (int i = tid; i < NTOK; i += 256) {
        float v = p[i];
        vals[cnt++] = v;
        mx = fmaxf(mx, v);
    }

    __shared__ float sh[8];
    #pragma unroll
    for (int o = 16; o; o >>= 1) mx = fmaxf(mx, __shfl_xor_sync(0xffffffffu, mx, o));
    if ((tid & 31) == 0) sh[tid >> 5] = mx;
    __syncthreads();
    float bm = -3.0e38f;
    #pragma unroll
    for (int i = 0; i < 8; ++i) bm = fmaxf(bm, sh[i]);
    __syncthreads();

    float sum = 0.f;
    for (int c = 0; c < cnt; ++c) {
        float e = __expf(vals[c] - bm);
        vals[c] = e;
        sum += e;
    }
    #pragma unroll
    for (int o = 16; o; o >>= 1) sum += __shfl_xor_sync(0xffffffffu, sum, o);
    if ((tid & 31) == 0) sh[tid >> 5] = sum;
    __syncthreads();
    float ts = 0.f;
    #pragma unroll
    for (int i = 0; i < 8; ++i) ts += sh[i];
    float inv = 1.0f / ts;

    cnt = 0;
    for (int i = tid; i < NTOK; i += 256) p[i] = vals[cnt++] * inv;
}

// ---------------------------------------------------------------------------
// out_h = attn @ v per (bt, h): (64x2112)@(2112x64). One block per bth.
// ---------------------------------------------------------------------------
__global__ void __launch_bounds__(256) av_kernel()
{
    int bth = blockIdx.x;
    int bt = bth >> 3, h = bth & 7;

    __shared__ float ps[64][65];
    __shared__ float vs[64][65];

    int tid = threadIdx.x;
    int ii = tid >> 4, dd = tid & 15;
    float acc[4][4] = {};

    for (int jc = 0; jc < NTOK / 64; ++jc) {
        int j0 = jc * 64;
        #pragma unroll
        for (int it = 0; it < 4; ++it) {
            int idx = tid + it * 256;
            int i = idx >> 4, q4 = (idx & 15) << 2;
            float4 v = *(const float4*)(g_sim + ((size_t)bth * NL + i) * NTOK + j0 + q4);
            ps[i][q4] = v.x; ps[i][q4 + 1] = v.y; ps[i][q4 + 2] = v.z; ps[i][q4 + 3] = v.w;
            float4 u = *(const float4*)(g_kv + (size_t)(bt * NTOK + j0 + i) * CDIM + INNER + h * DH + q4);
            vs[i][q4] = u.x; vs[i][q4 + 1] = u.y; vs[i][q4 + 2] = u.z; vs[i][q4 + 3] = u.w;
        }
        __syncthreads();

        #pragma unroll 16
        for (int j = 0; j < 64; ++j) {
            float ra[4], rb[4];
            #pragma unroll
            for (int a = 0; a < 4; ++a) ra[a] = ps[a * 16 + ii][j];
            #pragma unroll
            for (int c = 0; c < 4; ++c) rb[c] = vs[j][c * 16 + dd];
            #pragma unroll
            for (int a = 0; a < 4; ++a)
                #pragma unroll
                for (int c = 0; c < 4; ++c)
                    acc[a][c] += ra[a] * rb[c];
        }
        __syncthreads();
    }

    #pragma unroll
    for (int a = 0; a < 4; ++a)
        #pragma unroll
        for (int c = 0; c < 4; ++c) {
            int i = a * 16 + ii, d = c * 16 + dd;
            g_ao[(size_t)(bt * NL + i) * INNER + h * DH + d] = acc[a][c];
        }
}

// ---------------------------------------------------------------------------
// Launch — kernel launches only, no other runtime API calls (capture-safe).
// ---------------------------------------------------------------------------
extern "C" void kernel_launch(void* const* d_in, const int* in_sizes, int n_in,
                              void* d_out, int out_size)
{
    const float* x    = (const float*)d_in[0];
    const float* lat  = (const float*)d_in[1];
    const int*   mask = (const int*)  d_in[2];
    const float* mw   = (const float*)d_in[3];
    const float* mb   = (const float*)d_in[4];
    const float* lw   = (const float*)d_in[5];
    const float* lb   = (const float*)d_in[6];
    const float* Wq   = (const float*)d_in[7];
    const float* Wkv  = (const float*)d_in[8];
    const float* Wout = (const float*)d_in[9];

    // 1. LayerNorm (x + latents) -> g_kvin, g_lat
    ln_kernel<<<MROWS, 256>>>(x, lat, mw, mb, lw, lb);

    // 2. kv = kvin @ Wkv   (67584x1024)@(1024x1024)
    sgemm_kernel<0><<<dim3(1024 / 128, MROWS / 128), 256>>>(Wkv, nullptr, MROWS, 1024, 1024);

    // 3. q = lat @ Wq      (2048x1024)@(1024x512)
    sgemm_kernel<1><<<dim3(512 / 128, QROWS / 128), 256>>>(Wq, nullptr, QROWS, 512, 1024);

    // 4. sim = scale*q@k^T + mask
    sim_kernel<<<dim3(NBT * HEADS, NTOK / 64), 256>>>(mask);

    // 5. softmax rows
    softmax_kernel<<<NBT * HEADS * NL, 256>>>();

    // 6. attn @ v
    av_kernel<<<NBT * HEADS, 256>>>();

    // 7. out = ao @ Wout   (2048x512)@(512x1024)
    sgemm_kernel<2><<<dim3(1024 / 128, QROWS / 128), 256>>>(Wout, (float*)d_out, QROWS, 1024, 512);
}

// round 4
// speedup vs baseline: 1.1010x; 1.1010x over previous
#include <cuda_runtime.h>
#include <mma.h>
#include <cstddef>

using namespace nvcuda;

// Problem constants
#define CDIM   1024
#define NTOK   2112          // n + nl
#define NX     2048          // n
#define NL     64            // nl
#define NBT    32            // b*t
#define INNER  512           // heads*dim_head
#define HEADS  8
#define DH     64
#define MROWS  67584         // NBT * NTOK
#define QROWS  2048          // NBT * NL
#define SCALE  0.125f        // dh^-0.5

// Scratch (allocation-free rule: __device__ globals)
__device__ float g_kvin[(size_t)MROWS * CDIM];     // normalized concat(x, latents)
__device__ float g_kv  [(size_t)MROWS * CDIM];     // kvin @ Wkv
__device__ float g_lat [(size_t)QROWS * CDIM];     // normalized latents (contiguous)
__device__ float g_q   [(size_t)QROWS * INNER];    // (lat @ Wq) * SCALE
__device__ float g_sim [(size_t)NBT * HEADS * NL * NTOK]; // scores -> probs (in place)
__device__ float g_ao  [(size_t)QROWS * INNER];    // attn @ v

// ---------------------------------------------------------------------------
// LayerNorm: one block per row (1024 elems, 256 threads, float4)
// ---------------------------------------------------------------------------
__global__ void __launch_bounds__(256) ln_kernel(
    const float* __restrict__ x, const float* __restrict__ lat,
    const float* __restrict__ mw, const float* __restrict__ mb,
    const float* __restrict__ lw, const float* __restrict__ lb)
{
    int r   = blockIdx.x;
    int bt  = r / NTOK;
    int tok = r - bt * NTOK;

    const float *src, *w, *bias;
    float* dst2 = nullptr;
    if (tok < NX) {
        src = x + (size_t)(bt * NX + tok) * CDIM;
        w = mw; bias = mb;
    } else {
        int lr = bt * NL + (tok - NX);
        src = lat + (size_t)lr * CDIM;
        w = lw; bias = lb;
        dst2 = g_lat + (size_t)lr * CDIM;
    }
    float* dst = g_kvin + (size_t)r * CDIM;

    int tid = threadIdx.x;
    float4 v = ((const float4*)src)[tid];
    float s  = v.x + v.y + v.z + v.w;
    float ss = v.x*v.x + v.y*v.y + v.z*v.z + v.w*v.w;

    __shared__ float sh_s[8], sh_ss[8];
    #pragma unroll
    for (int o = 16; o; o >>= 1) {
        s  += __shfl_xor_sync(0xffffffffu, s,  o);
        ss += __shfl_xor_sync(0xffffffffu, ss, o);
    }
    if ((tid & 31) == 0) { sh_s[tid >> 5] = s; sh_ss[tid >> 5] = ss; }
    __syncthreads();
    float ts = 0.f, tss = 0.f;
    #pragma unroll
    for (int i = 0; i < 8; ++i) { ts += sh_s[i]; tss += sh_ss[i]; }

    float mean = ts * (1.0f / CDIM);
    float var  = tss * (1.0f / CDIM) - mean * mean;
    float inv  = rsqrtf(var + 1e-5f);

    float4 wv = ((const float4*)w)[tid];
    float4 bv = ((const float4*)bias)[tid];
    float4 o;
    o.x = (v.x - mean) * inv * wv.x + bv.x;
    o.y = (v.y - mean) * inv * wv.y + bv.y;
    o.z = (v.z - mean) * inv * wv.z + bv.z;
    o.w = (v.w - mean) * inv * wv.w + bv.w;
    ((float4*)dst)[tid] = o;
    if (dst2) ((float4*)dst2)[tid] = o;
}

// ---------------------------------------------------------------------------
// TF32 tensor-core GEMM via wmma: C(M,N) = A(M,K) @ B(K,N), row-major.
// Block tile 128x128, BK=32, 256 threads = 8 warps, warp tile 32x64.
// MODE 0: A=g_kvin, C=g_kv        MODE 1: A=g_lat, C=g_q (scaled by SCALE)
// Requires M%128==0, N%128==0, K%32==0.
// ---------------------------------------------------------------------------
#define A_LD 40
#define B_LD 136

template<int MODE>
__global__ void __launch_bounds__(256) tf32gemm_kernel(
    const float* __restrict__ Bw, int M, int N, int K)
{
    const float* A;
    float* C;
    if (MODE == 0) { A = g_kvin; C = g_kv; }
    else           { A = g_lat;  C = g_q;  }

    __shared__ float As[128 * A_LD];   // 128 rows x 32 cols (ld 40 = 160B, 16B-multiple)
    __shared__ float Bs[32 * B_LD];    // 32 rows x 128 cols (ld 136 = 544B, 16B-multiple)

    int tid = threadIdx.x;
    int warp = tid >> 5;
    int wm = warp & 3;                 // 0..3 -> m offset wm*32
    int wn = warp >> 2;                // 0..1 -> n offset wn*64
    int bx = blockIdx.x, by = blockIdx.y;

    const float* Ab = A  + (size_t)by * 128 * K;
    const float* Bb = Bw + bx * 128;

    wmma::fragment<wmma::accumulator, 16, 16, 8, float> cf[2][4];
    #pragma unroll
    for (int i = 0; i < 2; ++i)
        #pragma unroll
        for (int j = 0; j < 4; ++j)
            wmma::fill_fragment(cf[i][j], 0.0f);

    for (int k0 = 0; k0 < K; k0 += 32) {
        #pragma unroll
        for (int it = 0; it < 4; ++it) {
            int idx = tid + it * 256;      // 0..1023
            int ar = idx >> 3, ac4 = (idx & 7) << 2;
            float4 av = *(const float4*)(Ab + (size_t)ar * K + k0 + ac4);
            *(float4*)&As[ar * A_LD + ac4] = av;
            int br = idx >> 5, bc4 = (idx & 31) << 2;
            float4 bv = *(const float4*)(Bb + (size_t)(k0 + br) * N + bc4);
            *(float4*)&Bs[br * B_LD + bc4] = bv;
        }
        __syncthreads();

        #pragma unroll
        for (int ks = 0; ks < 4; ++ks) {
            wmma::fragment<wmma::matrix_a, 16, 16, 8, wmma::precision::tf32, wmma::row_major> af[2];
            wmma::fragment<wmma::matrix_b, 16, 16, 8, wmma::precision::tf32, wmma::row_major> bf[4];
            #pragma unroll
            for (int i = 0; i < 2; ++i) {
                wmma::load_matrix_sync(af[i], &As[(wm * 32 + i * 16) * A_LD + ks * 8], A_LD);
                #pragma unroll
                for (int e = 0; e < af[i].num_elements; ++e)
                    af[i].x[e] = wmma::__float_to_tf32(af[i].x[e]);
            }
            #pragma unroll
            for (int j = 0; j < 4; ++j) {
                wmma::load_matrix_sync(bf[j], &Bs[(ks * 8) * B_LD + wn * 64 + j * 16], B_LD);
                #pragma unroll
                for (int e = 0; e < bf[j].num_elements; ++e)
                    bf[j].x[e] = wmma::__float_to_tf32(bf[j].x[e]);
            }
            #pragma unroll
            for (int i = 0; i < 2; ++i)
                #pragma unroll
                for (int j = 0; j < 4; ++j)
                    wmma::mma_sync(cf[i][j], af[i], bf[j], cf[i][j]);
        }
        __syncthreads();
    }

    #pragma unroll
    for (int i = 0; i < 2; ++i)
        #pragma unroll
        for (int j = 0; j < 4; ++j) {
            if (MODE == 1) {   // fold q scale into the epilogue
                #pragma unroll
                for (int e = 0; e < cf[i][j].num_elements; ++e)
                    cf[i][j].x[e] *= SCALE;
            }
            float* Cp = C + (size_t)(by * 128 + wm * 32 + i * 16) * N
                          + bx * 128 + wn * 64 + j * 16;
            wmma::store_matrix_sync(Cp, cf[i][j], N, wmma::mem_row_major);
        }
}

// ---------------------------------------------------------------------------
// fp32 SIMT SGEMM for out-projection (precision headroom).
// A=g_ao, C=Cext. 128x128 tile, BK=8, 8x8 micro-tile, double-buffered.
// ---------------------------------------------------------------------------
__global__ void __launch_bounds__(256) sgemm_out_kernel(
    const float* __restrict__ Bw, float* __restrict__ Cext,
    int M, int N, int K)
{
    const float* A = g_ao;
    float* C = Cext;

    __shared__ float As[2][8][128];
    __shared__ float Bs[2][8][128];

    int tid = threadIdx.x;
    int bx = blockIdx.x, by = blockIdx.y;
    int tr = tid >> 4, tc = tid & 15;

    const float* Ab = A  + (size_t)by * 128 * K;
    const float* Bb = Bw + bx * 128;

    int a_row = tid >> 1;
    int a_col = (tid & 1) << 2;
    int b_row = tid >> 5;
    int b_col = (tid & 31) << 2;

    {
        float4 av = *(const float4*)(Ab + (size_t)a_row * K + a_col);
        As[0][a_col + 0][a_row] = av.x;
        As[0][a_col + 1][a_row] = av.y;
        As[0][a_col + 2][a_row] = av.z;
        As[0][a_col + 3][a_row] = av.w;
        *(float4*)&Bs[0][b_row][b_col] =
            *(const float4*)(Bb + (size_t)b_row * N + b_col);
    }
    __syncthreads();

    float acc[8][8] = {};
    int buf = 0;

    for (int k0 = 0; k0 < K; k0 += 8) {
        float4 an, bn;
        bool has_next = (k0 + 8) < K;
        if (has_next) {
            an = *(const float4*)(Ab + (size_t)a_row * K + (k0 + 8) + a_col);
            bn = *(const float4*)(Bb + (size_t)(k0 + 8 + b_row) * N + b_col);
        }

        #pragma unroll
        for (int k = 0; k < 8; ++k) {
            float ra[8], rb[8];
            *(float4*)(ra)     = *(const float4*)&As[buf][k][tr * 4];
            *(float4*)(ra + 4) = *(const float4*)&As[buf][k][64 + tr * 4];
            *(float4*)(rb)     = *(const float4*)&Bs[buf][k][tc * 4];
            *(float4*)(rb + 4) = *(const float4*)&Bs[buf][k][64 + tc * 4];
            #pragma unroll
            for (int i = 0; i < 8; ++i)
                #pragma unroll
                for (int j = 0; j < 8; ++j)
                    acc[i][j] += ra[i] * rb[j];
        }

        if (has_next) {
            As[buf ^ 1][a_col + 0][a_row] = an.x;
            As[buf ^ 1][a_col + 1][a_row] = an.y;
            As[buf ^ 1][a_col + 2][a_row] = an.z;
            As[buf ^ 1][a_col + 3][a_row] = an.w;
            *(float4*)&Bs[buf ^ 1][b_row][b_col] = bn;
        }
        __syncthreads();
        buf ^= 1;
    }

    #pragma unroll
    for (int i = 0; i < 8; ++i) {
        int r = (i < 4) ? (tr * 4 + i) : (64 + tr * 4 + (i - 4));
        float* Crow = C + (size_t)(by * 128 + r) * N + bx * 128;
        *(float4*)(Crow + tc * 4)      = make_float4(acc[i][0], acc[i][1], acc[i][2], acc[i][3]);
        *(float4*)(Crow + 64 + tc * 4) = make_float4(acc[i][4], acc[i][5], acc[i][6], acc[i][7]);
    }
}

// ---------------------------------------------------------------------------
// sim = q_scaled @ k^T + mask  per (bt, h); tiles of 64 keys.
// ---------------------------------------------------------------------------
__global__ void __launch_bounds__(256) sim_kernel(const int* __restrict__ mask)
{
    int bth = blockIdx.x, jc = blockIdx.y;
    int bt = bth >> 3, h = bth & 7;
    int b  = bt >> 2;
    int j0 = jc * 64;

    __shared__ float qs[64][65];
    __shared__ float ks[64][65];
    __shared__ float msk[64];

    int tid = threadIdx.x;
    #pragma unroll
    for (int it = 0; it < 4; ++it) {
        int idx = tid + it * 256;
        int i = idx >> 4, d4 = (idx & 15) << 2;
        float4 v = *(const float4*)(g_q + (size_t)(bt * NL + i) * INNER + h * DH + d4);
        qs[i][d4] = v.x; qs[i][d4 + 1] = v.y; qs[i][d4 + 2] = v.z; qs[i][d4 + 3] = v.w;
        float4 u = *(const float4*)(g_kv + (size_t)(bt * NTOK + j0 + i) * CDIM + h * DH + d4);
        ks[i][d4] = u.x; ks[i][d4 + 1] = u.y; ks[i][d4 + 2] = u.z; ks[i][d4 + 3] = u.w;
    }
    if (tid < 64) {
        int jg = j0 + tid;
        float m = 0.f;
        if (jg < NX && mask[b * NX + jg] == 1) m = -1e30f;
        msk[tid] = m;
    }
    __syncthreads();

    int ii = tid >> 4, jj = tid & 15;
    float acc[4][4] = {};
    #pragma unroll 16
    for (int d = 0; d < 64; ++d) {
        float ra[4], rb[4];
        #pragma unroll
        for (int a = 0; a < 4; ++a) ra[a] = qs[a * 16 + ii][d];
        #pragma unroll
        for (int c = 0; c < 4; ++c) rb[c] = ks[c * 16 + jj][d];
        #pragma unroll
        for (int a = 0; a < 4; ++a)
            #pragma unroll
            for (int c = 0; c < 4; ++c)
                acc[a][c] += ra[a] * rb[c];
    }

    #pragma unroll
    for (int a = 0; a < 4; ++a)
        #pragma unroll
        for (int c = 0; c < 4; ++c) {
            int i = a * 16 + ii, j = c * 16 + jj;
            g_sim[((size_t)bth * NL + i) * NTOK + j0 + j] = acc[a][c] + msk[j];
        }
}

// ---------------------------------------------------------------------------
// Row softmax over NTOK=2112, in place in g_sim.
// ---------------------------------------------------------------------------
__global__ void __launch_bounds__(256) softmax_kernel()
{
    int row = blockIdx.x;
    float* p = g_sim + (size_t)row * NTOK;
    int tid = threadIdx.x;

    float vals[9];
    int cnt = 0;
    float mx = -3.0e38f;
    for (int i = tid; i < NTOK; i += 256) {
        float v = p[i];
        vals[cnt++] = v;
        mx = fmaxf(mx, v);
    }

    __shared__ float sh[8];
    #pragma unroll
    for (int o = 16; o; o >>= 1) mx = fmaxf(mx, __shfl_xor_sync(0xffffffffu, mx, o));
    if ((tid & 31) == 0) sh[tid >> 5] = mx;
    __syncthreads();
    float bm = -3.0e38f;
    #pragma unroll
    for (int i = 0; i < 8; ++i) bm = fmaxf(bm, sh[i]);
    __syncthreads();

    float sum = 0.f;
    for (int c = 0; c < cnt; ++c) {
        float e = __expf(vals[c] - bm);
        vals[c] = e;
        sum += e;
    }
    #pragma unroll
    for (int o = 16; o; o >>= 1) sum += __shfl_xor_sync(0xffffffffu, sum, o);
    if ((tid & 31) == 0) sh[tid >> 5] = sum;
    __syncthreads();
    float ts = 0.f;
    #pragma unroll
    for (int i = 0; i < 8; ++i) ts += sh[i];
    float inv = 1.0f / ts;

    cnt = 0;
    for (int i = tid; i < NTOK; i += 256) p[i] = vals[cnt++] * inv;
}

// ---------------------------------------------------------------------------
// out_h = attn @ v per (bt, h): (64x2112)@(2112x64).
// ---------------------------------------------------------------------------
__global__ void __launch_bounds__(256) av_kernel()
{
    int bth = blockIdx.x;
    int bt = bth >> 3, h = bth & 7;

    __shared__ float ps[64][65];
    __shared__ float vs[64][65];

    int tid = threadIdx.x;
    int ii = tid >> 4, dd = tid & 15;
    float acc[4][4] = {};

    for (int jc = 0; jc < NTOK / 64; ++jc) {
        int j0 = jc * 64;
        #pragma unroll
        for (int it = 0; it < 4; ++it) {
            int idx = tid + it * 256;
            int i = idx >> 4, q4 = (idx & 15) << 2;
            float4 v = *(const float4*)(g_sim + ((size_t)bth * NL + i) * NTOK + j0 + q4);
            ps[i][q4] = v.x; ps[i][q4 + 1] = v.y; ps[i][q4 + 2] = v.z; ps[i][q4 + 3] = v.w;
            float4 u = *(const float4*)(g_kv + (size_t)(bt * NTOK + j0 + i) * CDIM + INNER + h * DH + q4);
            vs[i][q4] = u.x; vs[i][q4 + 1] = u.y; vs[i][q4 + 2] = u.z; vs[i][q4 + 3] = u.w;
        }
        __syncthreads();

        #pragma unroll 16
        for (int j = 0; j < 64; ++j) {
            float ra[4], rb[4];
            #pragma unroll
            for (int a = 0; a < 4; ++a) ra[a] = ps[a * 16 + ii][j];
            #pragma unroll
            for (int c = 0; c < 4; ++c) rb[c] = vs[j][c * 16 + dd];
            #pragma unroll
            for (int a = 0; a < 4; ++a)
                #pragma unroll
                for (int c = 0; c < 4; ++c)
                    acc[a][c] += ra[a] * rb[c];
        }
        __syncthreads();
    }

    #pragma unroll
    for (int a = 0; a < 4; ++a)
        #pragma unroll
        for (int c = 0; c < 4; ++c) {
            int i = a * 16 + ii, d = c * 16 + dd;
            g_ao[(size_t)(bt * NL + i) * INNER + h * DH + d] = acc[a][c];
        }
}

// ---------------------------------------------------------------------------
// Launch — kernel launches only (capture-safe).
// ---------------------------------------------------------------------------
extern "C" void kernel_launch(void* const* d_in, const int* in_sizes, int n_in,
                              void* d_out, int out_size)
{
    const float* x    = (const float*)d_in[0];
    const float* lat  = (const float*)d_in[1];
    const int*   mask = (const int*)  d_in[2];
    const float* mw   = (const float*)d_in[3];
    const float* mb   = (const float*)d_in[4];
    const float* lw   = (const float*)d_in[5];
    const float* lb   = (const float*)d_in[6];
    const float* Wq   = (const float*)d_in[7];
    const float* Wkv  = (const float*)d_in[8];
    const float* Wout = (const float*)d_in[9];

    // 1. LayerNorm (x + latents) -> g_kvin, g_lat
    ln_kernel<<<MROWS, 256>>>(x, lat, mw, mb, lw, lb);

    // 2. kv = kvin @ Wkv   (67584x1024)@(1024x1024)  [TF32 tensor cores]
    tf32gemm_kernel<0><<<dim3(1024 / 128, MROWS / 128), 256>>>(Wkv, MROWS, 1024, 1024);

    // 3. q = (lat @ Wq) * SCALE   (2048x1024)@(1024x512)  [TF32 tensor cores]
    tf32gemm_kernel<1><<<dim3(512 / 128, QROWS / 128), 256>>>(Wq, QROWS, 512, 1024);

    // 4. sim = q_scaled @ k^T + mask
    sim_kernel<<<dim3(NBT * HEADS, NTOK / 64), 256>>>(mask);

    // 5. softmax rows
    softmax_kernel<<<NBT * HEADS * NL, 256>>>();

    // 6. attn @ v
    av_kernel<<<NBT * HEADS, 256>>>();

    // 7. out = ao @ Wout   (2048x512)@(512x1024)     [fp32 SIMT]
    sgemm_out_kernel<<<dim3(1024 / 128, QROWS / 128), 256>>>(Wout, (float*)d_out, QROWS, 1024, 512);
}